// round 2
// baseline (speedup 1.0000x reference)
#include <cuda_runtime.h>
#include <math.h>

#define N_NODES 100000
#define N_EDGES 1600000
#define NUM_G   4096
#define EPSV    1e-5f

// ---------------- scratch (__device__ globals: allocation-free) ----------------
__device__ float  d_eemb[N_EDGES * 16];   // edge embeddings           102.4 MB
__device__ float  d_P[N_NODES * 256];     // per-node precomputed Wa·h 102.4 MB
__device__ float  d_h[N_NODES * 64];      // current node features
__device__ float  d_sum[N_NODES * 64];    // aggregation buffer
__device__ float  d_deg[N_NODES];
__device__ double d_stats[128];           // [0:64) sum, [64:128) sumsq
__device__ float  d_pool[NUM_G * 16];
__device__ float  d_pcnt[NUM_G];

// ---------------- degree ----------------
__global__ void k_deg(const int* __restrict__ dstp, float* __restrict__ deg) {
    int i = blockIdx.x * blockDim.x + threadIdx.x;
    if (i < N_EDGES) atomicAdd(&deg[dstp[i]], 1.0f);
}

// ---------------- edge embedding: e_emb = relu(edge_attr @ We + be) ----------------
__global__ void k_edge_emb(const float* __restrict__ ea, const float* __restrict__ We,
                           const float* __restrict__ be, float* __restrict__ out) {
    __shared__ float WeS[8 * 16];
    __shared__ float beS[16];
    int tid = threadIdx.x;
    if (tid < 128) WeS[tid] = We[tid];
    if (tid < 16)  beS[tid] = be[tid];
    __syncthreads();
    for (int e = blockIdx.x * blockDim.x + tid; e < N_EDGES; e += gridDim.x * blockDim.x) {
        float4 v0 = *(const float4*)&ea[e * 8];
        float4 v1 = *(const float4*)&ea[e * 8 + 4];
        float a[8] = {v0.x, v0.y, v0.z, v0.w, v1.x, v1.y, v1.z, v1.w};
        float o[16];
        #pragma unroll
        for (int j = 0; j < 16; j++) o[j] = beS[j];
        #pragma unroll
        for (int k = 0; k < 8; k++)
            #pragma unroll
            for (int j = 0; j < 16; j++) o[j] += a[k] * WeS[k * 16 + j];
        #pragma unroll
        for (int j = 0; j < 16; j++) o[j] = fmaxf(o[j], 0.0f);
        float4* op = (float4*)&out[e * 16];
        op[0] = make_float4(o[0], o[1], o[2], o[3]);
        op[1] = make_float4(o[4], o[5], o[6], o[7]);
        op[2] = make_float4(o[8], o[9], o[10], o[11]);
        op[3] = make_float4(o[12], o[13], o[14], o[15]);
    }
}

// ---------------- small node GEMM: C[n][c] = sum_k A[n][k] * W[(c/H1)*K + k][c%H1] ----------------
// 64 rows x 64 cols per block, 256 threads, 4x4 register tile per thread.
template<int K, int J, int H1, bool BR>
__global__ void __launch_bounds__(256) k_gemm_node(const float* __restrict__ A,
                                                   const float* __restrict__ W,
                                                   const float* __restrict__ bias,
                                                   float* __restrict__ C) {
    __shared__ float As[64 * K];
    __shared__ float Ws[K * 64];
    int tid = threadIdx.x;
    int n0  = blockIdx.x * 64;
    int cj0 = blockIdx.y * 64;
    for (int idx = tid; idx < K * 64; idx += 256) {
        int k = idx / 64, jj = idx % 64;
        int c = cj0 + jj;
        Ws[idx] = W[((c / H1) * K + k) * H1 + (c % H1)];
    }
    for (int idx = tid; idx < 64 * K; idx += 256) {
        int nl = idx / K, k = idx % K;
        int n = n0 + nl;
        As[idx] = (n < N_NODES) ? A[n * K + k] : 0.0f;
    }
    __syncthreads();
    int ty = tid / 16, tx = tid % 16;
    float acc[4][4];
    #pragma unroll
    for (int i = 0; i < 4; i++)
        #pragma unroll
        for (int j = 0; j < 4; j++) acc[i][j] = 0.0f;
    #pragma unroll 4
    for (int k = 0; k < K; k++) {
        float av[4];
        #pragma unroll
        for (int i = 0; i < 4; i++) av[i] = As[(ty + 16 * i) * K + k];
        float4 w = *(const float4*)&Ws[k * 64 + tx * 4];
        #pragma unroll
        for (int i = 0; i < 4; i++) {
            acc[i][0] += av[i] * w.x;
            acc[i][1] += av[i] * w.y;
            acc[i][2] += av[i] * w.z;
            acc[i][3] += av[i] * w.w;
        }
    }
    #pragma unroll
    for (int i = 0; i < 4; i++) {
        int n = n0 + ty + 16 * i;
        if (n < N_NODES) {
            float4 r;
            float v0 = acc[i][0], v1 = acc[i][1], v2 = acc[i][2], v3 = acc[i][3];
            if (BR) {
                int c = cj0 + tx * 4;
                v0 = fmaxf(v0 + bias[c + 0], 0.0f);
                v1 = fmaxf(v1 + bias[c + 1], 0.0f);
                v2 = fmaxf(v2 + bias[c + 2], 0.0f);
                v3 = fmaxf(v3 + bias[c + 3], 0.0f);
            }
            r.x = v0; r.y = v1; r.z = v2; r.w = v3;
            *(float4*)&C[n * J + cj0 + tx * 4] = r;
        }
    }
}

// ---------------- fused per-edge conv: hid = relu(P[dst]+P[src]+e@Wae+ba); out = hid@Wb+bb; scatter ----------------
template<int H1, int H2, int IN>
__global__ void __launch_bounds__(H1) k_conv_edge(const float* __restrict__ P,
                                                  const float* __restrict__ eemb,
                                                  const int* __restrict__ srcp,
                                                  const int* __restrict__ dstp,
                                                  const float* __restrict__ Wa,
                                                  const float* __restrict__ ba,
                                                  const float* __restrict__ Wb,
                                                  const float* __restrict__ bb,
                                                  float* __restrict__ sum) {
    static_assert(H1 == 2 * H2, "phase-2 split assumes H1 == 2*H2");
    constexpr int RS  = 2 * H1;
    constexpr int EPB = 256;
    __shared__ float WaeS[16 * H1];
    __shared__ float baS[H1];
    __shared__ float WbS[H1 * H2];
    __shared__ float bbS[H2];
    __shared__ float ebufS[2][16];
    __shared__ float hidS[2][H1];
    __shared__ float partS[2][H1];
    int tid = threadIdx.x;
    for (int i = tid; i < 16 * H1; i += H1) WaeS[i] = Wa[2 * IN * H1 + i];
    baS[tid] = ba[tid];
    for (int i = tid; i < H1 * H2; i += H1) WbS[i] = Wb[i];
    if (tid < H2) bbS[tid] = bb[tid];
    __syncthreads();

    int e0base = blockIdx.x * EPB;
    for (int it = 0; it < EPB / 2; ++it) {
        int e0 = e0base + it * 2;
        int e1 = e0 + 1;
        bool vA = (e0 < N_EDGES), vB = (e1 < N_EDGES);
        if (tid < 32) {
            int u = tid >> 4, k = tid & 15;
            int e = e0 + u;
            ebufS[u][k] = (e < N_EDGES) ? eemb[e * 16 + k] : 0.0f;
        }
        int dA = vA ? dstp[e0] : 0, sA = vA ? srcp[e0] : 0;
        int dB = vB ? dstp[e1] : 0, sB = vB ? srcp[e1] : 0;
        float pd0 = P[dA * RS + tid], ps0 = P[sA * RS + H1 + tid];
        float pd1 = P[dB * RS + tid], ps1 = P[sB * RS + H1 + tid];
        __syncthreads();
        float a0 = pd0 + ps0 + baS[tid];
        float a1 = pd1 + ps1 + baS[tid];
        #pragma unroll
        for (int k = 0; k < 16; k++) {
            float w = WaeS[k * H1 + tid];
            a0 += ebufS[0][k] * w;
            a1 += ebufS[1][k] * w;
        }
        hidS[0][tid] = fmaxf(a0, 0.0f);
        hidS[1][tid] = fmaxf(a1, 0.0f);
        __syncthreads();
        int half = tid / H2, o = tid % H2, jb = half * H2;
        float c0 = 0.0f, c1 = 0.0f;
        #pragma unroll
        for (int j = 0; j < H2; j++) {
            float w = WbS[(jb + j) * H2 + o];
            c0 += hidS[0][jb + j] * w;
            c1 += hidS[1][jb + j] * w;
        }
        partS[0][tid] = c0;
        partS[1][tid] = c1;
        __syncthreads();
        if (tid < H2) {
            if (vA) atomicAdd(&sum[dA * H2 + tid], partS[0][tid] + partS[0][tid + H2] + bbS[tid]);
            if (vB) atomicAdd(&sum[dB * H2 + tid], partS[1][tid] + partS[1][tid + H2] + bbS[tid]);
        }
        // no trailing sync needed: next iteration's writers are fenced by the syncs above
    }
}

// ---------------- mean-aggregate (in place) + BN statistics (double accumulate) ----------------
template<int F>
__global__ void __launch_bounds__(256) k_aggstat(float* __restrict__ sum,
                                                 const float* __restrict__ deg,
                                                 double* __restrict__ stats) {
    constexpr int R = 256 / F;
    __shared__ double sS[256];
    __shared__ double qS[256];
    int tid = threadIdx.x;
    int f = tid % F, r = tid / F;
    double s = 0.0, q = 0.0;
    for (int n = blockIdx.x * R + r; n < N_NODES; n += gridDim.x * R) {
        float inv = 1.0f / fmaxf(deg[n], 1.0f);
        float v = sum[n * F + f] * inv;
        sum[n * F + f] = v;
        s += v;
        q += (double)v * (double)v;
    }
    sS[tid] = s; qS[tid] = q;
    __syncthreads();
    #pragma unroll
    for (int off = 128; off >= F; off >>= 1) {
        if (tid < off) { sS[tid] += sS[tid + off]; qS[tid] += qS[tid + off]; }
        __syncthreads();
    }
    if (tid < F) {
        atomicAdd(&stats[f], sS[tid]);
        atomicAdd(&stats[64 + f], qS[tid]);
    }
}

// ---------------- batchnorm + relu ----------------
template<int F>
__global__ void k_bnrelu(const float* __restrict__ sum, const double* __restrict__ stats,
                         const float* __restrict__ g, const float* __restrict__ b,
                         float* __restrict__ h) {
    int i = blockIdx.x * blockDim.x + threadIdx.x;
    if (i >= N_NODES * F) return;
    int f = i % F;
    float mu  = (float)(stats[f] / (double)N_NODES);
    float var = (float)(stats[64 + f] / (double)N_NODES) - mu * mu;
    float y = (sum[i] - mu) * rsqrtf(fmaxf(var, 0.0f) + EPSV) * g[f] + b[f];
    h[i] = fmaxf(y, 0.0f);
}

// ---------------- global mean pool ----------------
__global__ void k_pool(const float* __restrict__ h, const int* __restrict__ batch,
                       float* __restrict__ pool, float* __restrict__ pcnt) {
    int i = blockIdx.x * blockDim.x + threadIdx.x;
    if (i >= N_NODES * 16) return;
    int n = i >> 4, f = i & 15;
    int g = batch[n];
    atomicAdd(&pool[g * 16 + f], h[i]);
    if (f == 0) atomicAdd(&pcnt[g], 1.0f);
}

// ---------------- final fc + sigmoid ----------------
__global__ void k_final(const float* __restrict__ pool, const float* __restrict__ pcnt,
                        const float* __restrict__ Wfc, const float* __restrict__ bfc,
                        float* __restrict__ out) {
    int i = blockIdx.x * blockDim.x + threadIdx.x;
    if (i >= NUM_G * 12) return;
    int g = i / 12, t = i % 12;
    float inv = 1.0f / fmaxf(pcnt[g], 1.0f);
    float acc = bfc[t];
    #pragma unroll
    for (int f = 0; f < 16; f++) acc += pool[g * 16 + f] * inv * Wfc[f * 12 + t];
    out[i] = 1.0f / (1.0f + expf(-acc));
}

// ---------------- launcher ----------------
extern "C" void kernel_launch(void* const* d_in, const int* in_sizes, int n_in,
                              void* d_out, int out_size) {
    const float* x     = (const float*)d_in[0];
    const float* ea    = (const float*)d_in[1];
    const int*   ei    = (const int*)d_in[2];
    const int*   batch = (const int*)d_in[3];
    // num_graphs may or may not appear as input 4 (scalar). Detect: Wn has 32*64=2048 elems.
    int wo = (in_sizes[4] == 2048) ? 4 : 5;
    const float* Wn  = (const float*)d_in[wo + 0];
    const float* bn_ = (const float*)d_in[wo + 1];
    const float* We  = (const float*)d_in[wo + 2];
    const float* be_ = (const float*)d_in[wo + 3];
    const float* W1a = (const float*)d_in[wo + 4];
    const float* b1a = (const float*)d_in[wo + 5];
    const float* W1b = (const float*)d_in[wo + 6];
    const float* b1b = (const float*)d_in[wo + 7];
    const float* W2a = (const float*)d_in[wo + 8];
    const float* b2a = (const float*)d_in[wo + 9];
    const float* W2b = (const float*)d_in[wo + 10];
    const float* b2b = (const float*)d_in[wo + 11];
    const float* W3a = (const float*)d_in[wo + 12];
    const float* b3a = (const float*)d_in[wo + 13];
    const float* W3b = (const float*)d_in[wo + 14];
    const float* b3b = (const float*)d_in[wo + 15];
    const float* g1  = (const float*)d_in[wo + 16];
    const float* be1 = (const float*)d_in[wo + 17];
    const float* g2  = (const float*)d_in[wo + 18];
    const float* be2 = (const float*)d_in[wo + 19];
    const float* g3  = (const float*)d_in[wo + 20];
    const float* be3 = (const float*)d_in[wo + 21];
    const float* Wfc = (const float*)d_in[wo + 22];
    const float* bfc = (const float*)d_in[wo + 23];
    float* out = (float*)d_out;

    const int* srcp = ei;
    const int* dstp = ei + N_EDGES;

    void *p_eemb, *p_P, *p_h, *p_sum, *p_deg, *p_stats, *p_pool, *p_pcnt;
    cudaGetSymbolAddress(&p_eemb, d_eemb);
    cudaGetSymbolAddress(&p_P, d_P);
    cudaGetSymbolAddress(&p_h, d_h);
    cudaGetSymbolAddress(&p_sum, d_sum);
    cudaGetSymbolAddress(&p_deg, d_deg);
    cudaGetSymbolAddress(&p_stats, d_stats);
    cudaGetSymbolAddress(&p_pool, d_pool);
    cudaGetSymbolAddress(&p_pcnt, d_pcnt);
    float*  eemb  = (float*)p_eemb;
    float*  P     = (float*)p_P;
    float*  h     = (float*)p_h;
    float*  sum   = (float*)p_sum;
    float*  deg   = (float*)p_deg;
    double* stats = (double*)p_stats;
    float*  pool  = (float*)p_pool;
    float*  pcnt  = (float*)p_pcnt;

    const int NB64 = (N_NODES + 63) / 64;  // 1563
    const int EB   = (N_EDGES + 255) / 256; // 6250

    // prologue
    cudaMemsetAsync(p_deg, 0, N_NODES * sizeof(float));
    cudaMemsetAsync(p_pool, 0, NUM_G * 16 * sizeof(float));
    cudaMemsetAsync(p_pcnt, 0, NUM_G * sizeof(float));
    k_deg<<<EB, 256>>>(dstp, deg);
    k_edge_emb<<<2048, 256>>>(ea, We, be_, eemb);
    k_gemm_node<32, 64, 64, true><<<dim3(NB64, 1), 256>>>(x, Wn, bn_, h);

    // conv1: 64 -> (144->128->64)
    k_gemm_node<64, 256, 128, false><<<dim3(NB64, 4), 256>>>(h, W1a, nullptr, P);
    cudaMemsetAsync(p_sum, 0, N_NODES * 64 * sizeof(float));
    k_conv_edge<128, 64, 64><<<EB, 128>>>(P, eemb, srcp, dstp, W1a, b1a, W1b, b1b, sum);
    cudaMemsetAsync(p_stats, 0, 128 * sizeof(double));
    k_aggstat<64><<<512, 256>>>(sum, deg, stats);
    k_bnrelu<64><<<(N_NODES * 64 + 255) / 256, 256>>>(sum, stats, g1, be1, h);

    // conv2: 64 -> (144->64->32)
    k_gemm_node<64, 128, 64, false><<<dim3(NB64, 2), 256>>>(h, W2a, nullptr, P);
    cudaMemsetAsync(p_sum, 0, N_NODES * 32 * sizeof(float));
    k_conv_edge<64, 32, 64><<<EB, 64>>>(P, eemb, srcp, dstp, W2a, b2a, W2b, b2b, sum);
    cudaMemsetAsync(p_stats, 0, 128 * sizeof(double));
    k_aggstat<32><<<512, 256>>>(sum, deg, stats);
    k_bnrelu<32><<<(N_NODES * 32 + 255) / 256, 256>>>(sum, stats, g2, be2, h);

    // conv3: 32 -> (80->32->16)
    k_gemm_node<32, 64, 32, false><<<dim3(NB64, 1), 256>>>(h, W3a, nullptr, P);
    cudaMemsetAsync(p_sum, 0, N_NODES * 16 * sizeof(float));
    k_conv_edge<32, 16, 32><<<EB, 32>>>(P, eemb, srcp, dstp, W3a, b3a, W3b, b3b, sum);
    cudaMemsetAsync(p_stats, 0, 128 * sizeof(double));
    k_aggstat<16><<<512, 256>>>(sum, deg, stats);
    k_bnrelu<16><<<(N_NODES * 16 + 255) / 256, 256>>>(sum, stats, g3, be3, h);

    // pool + fc + sigmoid
    k_pool<<<(N_NODES * 16 + 255) / 256, 256>>>(h, batch, pool, pcnt);
    k_final<<<(NUM_G * 12 + 255) / 256, 256>>>(pool, pcnt, Wfc, bfc, out);
}